// round 6
// baseline (speedup 1.0000x reference)
#include <cuda_runtime.h>
#include <cstdint>

#define THREADS 256
#define BM 128
#define BN 64
#define DH 64
#define SQ 4096
#define SKV 4096
#define NT (SKV / BN)
#define BATCH 4

// smem: double-buffered V tiles. buf k at k*16384: vh @ +0 (64 rows x 128B), vl @ +8192
#define BUF_STRIDE 16384
#define VL_OFF 8192
#define SMEM_TOTAL 32768

// pre-split V in bf16x2 form (element pairs), 2MB each
__device__ uint32_t g_vh[(size_t)BATCH * SKV * DH / 2];
__device__ uint32_t g_vl[(size_t)BATCH * SKV * DH / 2];

extern __shared__ char smem_raw[];

__device__ __forceinline__ uint32_t su32(const void* p) {
    uint32_t a;
    asm("{ .reg .u64 t; cvta.to.shared.u64 t, %1; cvt.u32.u64 %0, t; }" : "=r"(a) : "l"(p));
    return a;
}
__device__ __forceinline__ uint32_t cvt2bf(float hi, float lo) {
    uint32_t r;
    asm("cvt.rn.bf16x2.f32 %0, %1, %2;" : "=r"(r) : "f"(hi), "f"(lo));
    return r;
}
__device__ __forceinline__ void ldsm4(uint32_t& r0, uint32_t& r1, uint32_t& r2, uint32_t& r3, uint32_t a) {
    asm volatile("ldmatrix.sync.aligned.m8n8.x4.shared.b16 {%0,%1,%2,%3}, [%4];"
                 : "=r"(r0), "=r"(r1), "=r"(r2), "=r"(r3) : "r"(a));
}
__device__ __forceinline__ void ldsm4t(uint32_t& r0, uint32_t& r1, uint32_t& r2, uint32_t& r3, uint32_t a) {
    asm volatile("ldmatrix.sync.aligned.m8n8.x4.trans.shared.b16 {%0,%1,%2,%3}, [%4];"
                 : "=r"(r0), "=r"(r1), "=r"(r2), "=r"(r3) : "r"(a));
}
__device__ __forceinline__ void mma16816(float* d, const uint32_t* a, uint32_t b0, uint32_t b1) {
    asm volatile("mma.sync.aligned.m16n8k16.row.col.f32.bf16.bf16.f32 "
                 "{%0,%1,%2,%3}, {%4,%5,%6,%7}, {%8,%9}, {%0,%1,%2,%3};"
                 : "+f"(d[0]), "+f"(d[1]), "+f"(d[2]), "+f"(d[3])
                 : "r"(a[0]), "r"(a[1]), "r"(a[2]), "r"(a[3]), "r"(b0), "r"(b1));
}
__device__ __forceinline__ void split4(float4 v, uint32_t& h01, uint32_t& h23, uint32_t& l01, uint32_t& l23) {
    h01 = cvt2bf(v.y, v.x);
    h23 = cvt2bf(v.w, v.z);
    float r0 = v.x - __uint_as_float(h01 << 16);
    float r1 = v.y - __uint_as_float(h01 & 0xFFFF0000u);
    float r2 = v.z - __uint_as_float(h23 << 16);
    float r3 = v.w - __uint_as_float(h23 & 0xFFFF0000u);
    l01 = cvt2bf(r1, r0);
    l23 = cvt2bf(r3, r2);
}
__device__ __forceinline__ void cpasync16(uint32_t dst, const uint32_t* src) {
    asm volatile("cp.async.cg.shared.global [%0], [%1], 16;" :: "r"(dst), "l"(src) : "memory");
}

// ---------------- pre-kernel: V -> (vh, vl) bf16 split ----------------
__global__ void __launch_bounds__(256)
vconv(const float* __restrict__ V)
{
    int i = blockIdx.x * 256 + threadIdx.x;        // float4 index over BATCH*SKV*DH/4
    float4 v = ((const float4*)V)[i];
    uint32_t h01, h23, l01, l23;
    split4(v, h01, h23, l01, l23);
    g_vh[2 * i] = h01; g_vh[2 * i + 1] = h23;
    g_vl[2 * i] = l01; g_vl[2 * i + 1] = l23;
}

// ---------------- main kernel ----------------
__global__ void __launch_bounds__(THREADS)
attn_hmma(const float* __restrict__ Q, float* __restrict__ O)
{
    const uint32_t sb = su32(smem_raw);
    const int tid = threadIdx.x;
    const int w = tid >> 5;
    const int lane = tid & 31;
    const int bq = blockIdx.x, b = blockIdx.y;

    const float* Qg = Q + ((size_t)b * SQ + (size_t)bq * BM) * DH;
    float* Og = O + ((size_t)b * SQ + (size_t)bq * BM) * DH;
    const size_t vbase = ((size_t)b * SKV) * (DH / 2);   // uint32 units

    // ---------------- stage Q -> A-fragments (qh, ql), two passes through buf0 smem ----------------
    uint32_t qh[4][4], ql[4][4];
    {
        uint2 lres[8];
        #pragma unroll
        for (int s = 0; s < 8; s++) {
            int idx = tid + THREADS * s;          // float4 idx over 128x16
            int row = idx >> 4, c4 = idx & 15;
            float4 v = *(const float4*)(Qg + row * DH + c4 * 4);
            uint32_t h01, h23, l01, l23;
            split4(v, h01, h23, l01, l23);
            *(uint2*)(smem_raw + row * 128 + ((c4 * 8) ^ ((row & 7) << 4))) = make_uint2(h01, h23);
            lres[s] = make_uint2(l01, l23);
        }
        __syncthreads();
        int arow = w * 16 + (lane & 7) + ((lane >> 3) & 1) * 8;
        uint32_t abase = sb + arow * 128;
        uint32_t axor = (arow & 7) << 4;
        #pragma unroll
        for (int kf = 0; kf < 4; kf++) {
            uint32_t addr = abase + ((kf * 32 + (lane >> 4) * 16) ^ axor);
            ldsm4(qh[kf][0], qh[kf][1], qh[kf][2], qh[kf][3], addr);
        }
        __syncthreads();
        #pragma unroll
        for (int s = 0; s < 8; s++) {
            int idx = tid + THREADS * s;
            int row = idx >> 4, c4 = idx & 15;
            *(uint2*)(smem_raw + row * 128 + ((c4 * 8) ^ ((row & 7) << 4))) = lres[s];
        }
        __syncthreads();
        #pragma unroll
        for (int kf = 0; kf < 4; kf++) {
            uint32_t addr = abase + ((kf * 32 + (lane >> 4) * 16) ^ axor);
            ldsm4(ql[kf][0], ql[kf][1], ql[kf][2], ql[kf][3], addr);
        }
        __syncthreads();   // all warps done reading buf0 region before cp.async overwrites it
    }

    // ---------------- persistent state ----------------
    float o[8][4];
    #pragma unroll
    for (int i = 0; i < 8; i++)
        #pragma unroll
        for (int j = 0; j < 4; j++) o[i][j] = 0.0f;
    float lsum0 = 0.0f, lsum1 = 0.0f;

    // GEMM1 B addresses (buffer-relative; XOR applied after full column combine)
    const uint32_t lxor = (lane & 7) << 4;
    const uint32_t g1k = (lane & 7) * 128;
    const uint32_t g1a = sb + g1k + (((lane >> 3) * 16) ^ lxor);
    const uint32_t g1b = sb + g1k + ((64 + (lane >> 3) * 16) ^ lxor);
    // GEMM2 (trans): key-row base separate; in-row offset XORed per fragment
    const uint32_t g2rowbase = sb + ((lane & 7) + 8 * ((lane >> 3) & 1)) * 128;
    const uint32_t g2klo = (lane >> 4) * 16;

    // per-thread cp.async chunk coords (2 chunks per tensor per tile)
    // chunk id = tid + 256*s over 512 chunks: row = id>>3, c = id&7
    const int id0 = tid, id1 = tid + 256;
    const int r0c = id0 >> 3, c0c = id0 & 7;
    const int r1c = id1 >> 3, c1c = id1 & 7;
    const uint32_t d0 = r0c * 128 + ((c0c * 16) ^ ((r0c & 7) << 4));
    const uint32_t d1 = r1c * 128 + ((c1c * 16) ^ ((r1c & 7) << 4));
    const uint32_t s0 = r0c * 32 + c0c * 4;    // uint32 offset within tile
    const uint32_t s1 = r1c * 32 + c1c * 4;

    // prologue: issue tile 0 into buf 0
    {
        size_t g = vbase;
        cpasync16(sb + d0, g_vh + g + s0);
        cpasync16(sb + VL_OFF + d0, g_vl + g + s0);
        cpasync16(sb + d1, g_vh + g + s1);
        cpasync16(sb + VL_OFF + d1, g_vl + g + s1);
        asm volatile("cp.async.commit_group;" ::: "memory");
    }

    for (int t = 0; t < NT; t++) {
        asm volatile("cp.async.wait_group 0;" ::: "memory");
        __syncthreads();
        if (t + 1 < NT) {
            uint32_t nb = sb + ((t + 1) & 1) * BUF_STRIDE;
            size_t g = vbase + (size_t)(t + 1) * BN * (DH / 2);
            cpasync16(nb + d0, g_vh + g + s0);
            cpasync16(nb + VL_OFF + d0, g_vl + g + s0);
            cpasync16(nb + d1, g_vh + g + s1);
            cpasync16(nb + VL_OFF + d1, g_vl + g + s1);
            asm volatile("cp.async.commit_group;" ::: "memory");
        }
        const uint32_t bo = (t & 1) * BUF_STRIDE;

        // ---- GEMM1: S[16 x 64] = qh.vh^T + qh.vl^T + ql.vh^T ----
        float sfrag[8][4];
        #pragma unroll
        for (int i = 0; i < 8; i++)
            #pragma unroll
            for (int j = 0; j < 4; j++) sfrag[i][j] = 0.0f;
        #pragma unroll
        for (int nf = 0; nf < 8; nf++) {
            uint32_t bh[4], bh2[4], bl[4], bl2[4];
            ldsm4(bh[0], bh[1], bh2[0], bh2[1], g1a + bo + nf * 1024);
            ldsm4(bh[2], bh[3], bh2[2], bh2[3], g1b + bo + nf * 1024);
            ldsm4(bl[0], bl[1], bl2[0], bl2[1], g1a + bo + VL_OFF + nf * 1024);
            ldsm4(bl[2], bl[3], bl2[2], bl2[3], g1b + bo + VL_OFF + nf * 1024);
            mma16816(sfrag[nf], qh[0], bh[0], bh[1]);
            mma16816(sfrag[nf], qh[1], bh2[0], bh2[1]);
            mma16816(sfrag[nf], qh[2], bh[2], bh[3]);
            mma16816(sfrag[nf], qh[3], bh2[2], bh2[3]);
            mma16816(sfrag[nf], qh[0], bl[0], bl[1]);
            mma16816(sfrag[nf], qh[1], bl2[0], bl2[1]);
            mma16816(sfrag[nf], qh[2], bl[2], bl[3]);
            mma16816(sfrag[nf], qh[3], bl2[2], bl2[3]);
            mma16816(sfrag[nf], ql[0], bh[0], bh[1]);
            mma16816(sfrag[nf], ql[1], bh2[0], bh2[1]);
            mma16816(sfrag[nf], ql[2], bh[2], bh[3]);
            mma16816(sfrag[nf], ql[3], bh2[2], bh2[3]);
        }

        // ---- softmax (unnormalized exp, no max-sub) -> P A-frags (ph, pl) ----
        uint32_t ph[4][4], pl[4][4];
        #pragma unroll
        for (int sf = 0; sf < 8; sf++) {
            float e0 = __expf(sfrag[sf][0]);
            float e1 = __expf(sfrag[sf][1]);
            float e2 = __expf(sfrag[sf][2]);
            float e3 = __expf(sfrag[sf][3]);
            lsum0 += e0 + e1;
            lsum1 += e2 + e3;
            uint32_t h01 = cvt2bf(e1, e0);
            uint32_t h23 = cvt2bf(e3, e2);
            float r0 = e0 - __uint_as_float(h01 << 16);
            float r1 = e1 - __uint_as_float(h01 & 0xFFFF0000u);
            float r2 = e2 - __uint_as_float(h23 << 16);
            float r3 = e3 - __uint_as_float(h23 & 0xFFFF0000u);
            int kf = sf >> 1, hh = (sf & 1) * 2;
            ph[kf][hh] = h01;
            ph[kf][hh + 1] = h23;
            pl[kf][hh] = cvt2bf(r1, r0);
            pl[kf][hh + 1] = cvt2bf(r3, r2);
        }

        // ---- GEMM2: O[16 x 64] += ph.vh + ph.vl + pl.vh  (trans B) ----
        #pragma unroll
        for (int kf = 0; kf < 4; kf++) {
            uint32_t kfo = bo + (uint32_t)kf * 2048;
            #pragma unroll
            for (int dh2 = 0; dh2 < 4; dh2++) {
                uint32_t inrow = (uint32_t)((dh2 * 32 + g2klo) ^ lxor);
                uint32_t hr0, hr1, hr2, hr3, lr0, lr1, lr2, lr3;
                ldsm4t(hr0, hr1, hr2, hr3, g2rowbase + kfo + inrow);
                ldsm4t(lr0, lr1, lr2, lr3, g2rowbase + kfo + VL_OFF + inrow);
                mma16816(o[2 * dh2], ph[kf], hr0, hr1);
                mma16816(o[2 * dh2], ph[kf], lr0, lr1);
                mma16816(o[2 * dh2], pl[kf], hr0, hr1);
                mma16816(o[2 * dh2 + 1], ph[kf], hr2, hr3);
                mma16816(o[2 * dh2 + 1], ph[kf], lr2, lr3);
                mma16816(o[2 * dh2 + 1], pl[kf], hr2, hr3);
            }
        }
    }

    // ---------------- epilogue ----------------
    lsum0 += __shfl_xor_sync(0xffffffffu, lsum0, 1);
    lsum0 += __shfl_xor_sync(0xffffffffu, lsum0, 2);
    lsum1 += __shfl_xor_sync(0xffffffffu, lsum1, 1);
    lsum1 += __shfl_xor_sync(0xffffffffu, lsum1, 2);
    float inv0 = 1.0f / lsum0;
    float inv1 = 1.0f / lsum1;

    int r0 = w * 16 + (lane >> 2);
    float2* op0 = (float2*)(Og + (size_t)r0 * DH);
    float2* op1 = (float2*)(Og + (size_t)(r0 + 8) * DH);
    #pragma unroll
    for (int nf = 0; nf < 8; nf++) {
        int c2 = nf * 4 + (lane & 3);
        op0[c2] = make_float2(o[nf][0] * inv0, o[nf][1] * inv0);
        op1[c2] = make_float2(o[nf][2] * inv1, o[nf][3] * inv1);
    }
}

extern "C" void kernel_launch(void* const* d_in, const int* in_sizes, int n_in,
                              void* d_out, int out_size)
{
    const float* Q = (const float*)d_in[0];   // query [4,4096,64] fp32
    const float* V = (const float*)d_in[1];   // value [4,4096,64] fp32
    float* O = (float*)d_out;                 // out   [4,4096,64] fp32

    // pre-split V into bf16 high/low tensors (amortized across all 32 query-tile CTAs/batch)
    vconv<<<(BATCH * SKV * DH / 4) / 256, 256>>>(V);

    dim3 grid(SQ / BM, BATCH);
    attn_hmma<<<grid, THREADS, SMEM_TOTAL>>>(Q, O);
}

// round 7
// speedup vs baseline: 1.1297x; 1.1297x over previous
#include <cuda_runtime.h>
#include <cstdint>

#define THREADS 256
#define BM 128
#define BN 64
#define DH 64
#define SQ 4096
#define SKV 4096
#define NT (SKV / BN)
#define BATCH 4

// smem: double-buffered V tiles. buf k at k*16384: vh @ +0 (64 rows x 128B), vl @ +8192
// epilogue reuse: O exchange 32KB @0, lsum 512B @32768
#define BUF_STRIDE 16384
#define VL_OFF 8192
#define LS_OFF 32768
#define SMEM_TOTAL 33280

// pre-split V in bf16x2 form (element pairs), 2MB each
__device__ uint32_t g_vh[(size_t)BATCH * SKV * DH / 2];
__device__ uint32_t g_vl[(size_t)BATCH * SKV * DH / 2];

extern __shared__ char smem_raw[];

__device__ __forceinline__ uint32_t su32(const void* p) {
    uint32_t a;
    asm("{ .reg .u64 t; cvta.to.shared.u64 t, %1; cvt.u32.u64 %0, t; }" : "=r"(a) : "l"(p));
    return a;
}
__device__ __forceinline__ uint32_t cvt2bf(float hi, float lo) {
    uint32_t r;
    asm("cvt.rn.bf16x2.f32 %0, %1, %2;" : "=r"(r) : "f"(hi), "f"(lo));
    return r;
}
__device__ __forceinline__ void ldsm4(uint32_t& r0, uint32_t& r1, uint32_t& r2, uint32_t& r3, uint32_t a) {
    asm volatile("ldmatrix.sync.aligned.m8n8.x4.shared.b16 {%0,%1,%2,%3}, [%4];"
                 : "=r"(r0), "=r"(r1), "=r"(r2), "=r"(r3) : "r"(a));
}
__device__ __forceinline__ void ldsm4t(uint32_t& r0, uint32_t& r1, uint32_t& r2, uint32_t& r3, uint32_t a) {
    asm volatile("ldmatrix.sync.aligned.m8n8.x4.trans.shared.b16 {%0,%1,%2,%3}, [%4];"
                 : "=r"(r0), "=r"(r1), "=r"(r2), "=r"(r3) : "r"(a));
}
__device__ __forceinline__ void mma16816(float* d, const uint32_t* a, uint32_t b0, uint32_t b1) {
    asm volatile("mma.sync.aligned.m16n8k16.row.col.f32.bf16.bf16.f32 "
                 "{%0,%1,%2,%3}, {%4,%5,%6,%7}, {%8,%9}, {%0,%1,%2,%3};"
                 : "+f"(d[0]), "+f"(d[1]), "+f"(d[2]), "+f"(d[3])
                 : "r"(a[0]), "r"(a[1]), "r"(a[2]), "r"(a[3]), "r"(b0), "r"(b1));
}
__device__ __forceinline__ void split4(float4 v, uint32_t& h01, uint32_t& h23, uint32_t& l01, uint32_t& l23) {
    h01 = cvt2bf(v.y, v.x);
    h23 = cvt2bf(v.w, v.z);
    float r0 = v.x - __uint_as_float(h01 << 16);
    float r1 = v.y - __uint_as_float(h01 & 0xFFFF0000u);
    float r2 = v.z - __uint_as_float(h23 << 16);
    float r3 = v.w - __uint_as_float(h23 & 0xFFFF0000u);
    l01 = cvt2bf(r1, r0);
    l23 = cvt2bf(r3, r2);
}
__device__ __forceinline__ void cpasync16(uint32_t dst, const uint32_t* src) {
    asm volatile("cp.async.cg.shared.global [%0], [%1], 16;" :: "r"(dst), "l"(src) : "memory");
}

// ---------------- pre-kernel: V -> (vh, vl) bf16 split ----------------
__global__ void __launch_bounds__(256)
vconv(const float* __restrict__ V)
{
    int i = blockIdx.x * 256 + threadIdx.x;
    float4 v = ((const float4*)V)[i];
    uint32_t h01, h23, l01, l23;
    split4(v, h01, h23, l01, l23);
    g_vh[2 * i] = h01; g_vh[2 * i + 1] = h23;
    g_vl[2 * i] = l01; g_vl[2 * i + 1] = l23;
}

// ---------------- main kernel ----------------
__global__ void __launch_bounds__(THREADS, 1)
attn_hmma(const float* __restrict__ Q, float* __restrict__ O)
{
    const uint32_t sb = su32(smem_raw);
    const int tid = threadIdx.x;
    const int w = tid >> 5;
    const int lane = tid & 31;
    const int rg = w & 3;          // row group: 32 query rows
    const int kh = w >> 2;         // key half: 32 of 64 keys
    const int bq = blockIdx.x, b = blockIdx.y;

    const float* Qg = Q + ((size_t)b * SQ + (size_t)bq * BM) * DH;
    float* Og = O + ((size_t)b * SQ + (size_t)bq * BM) * DH;
    const size_t vbase = ((size_t)b * SKV) * (DH / 2);   // uint32 units

    // ---------------- stage Q -> A-fragments qh/ql [mf][kf][4] ----------------
    uint32_t qh[2][4][4], ql[2][4][4];
    {
        uint2 lres[8];
        #pragma unroll
        for (int s = 0; s < 8; s++) {
            int idx = tid + THREADS * s;          // float4 idx over 128x16
            int row = idx >> 4, c4 = idx & 15;
            float4 v = *(const float4*)(Qg + row * DH + c4 * 4);
            uint32_t h01, h23, l01, l23;
            split4(v, h01, h23, l01, l23);
            *(uint2*)(smem_raw + row * 128 + ((c4 * 8) ^ ((row & 7) << 4))) = make_uint2(h01, h23);
            lres[s] = make_uint2(l01, l23);
        }
        __syncthreads();
        #pragma unroll
        for (int mf = 0; mf < 2; mf++) {
            int arow = rg * 32 + mf * 16 + (lane & 7) + ((lane >> 3) & 1) * 8;
            uint32_t abase = sb + arow * 128;
            uint32_t axor = (arow & 7) << 4;
            #pragma unroll
            for (int kf = 0; kf < 4; kf++) {
                uint32_t addr = abase + ((kf * 32 + (lane >> 4) * 16) ^ axor);
                ldsm4(qh[mf][kf][0], qh[mf][kf][1], qh[mf][kf][2], qh[mf][kf][3], addr);
            }
        }
        __syncthreads();
        #pragma unroll
        for (int s = 0; s < 8; s++) {
            int idx = tid + THREADS * s;
            int row = idx >> 4, c4 = idx & 15;
            *(uint2*)(smem_raw + row * 128 + ((c4 * 8) ^ ((row & 7) << 4))) = lres[s];
        }
        __syncthreads();
        #pragma unroll
        for (int mf = 0; mf < 2; mf++) {
            int arow = rg * 32 + mf * 16 + (lane & 7) + ((lane >> 3) & 1) * 8;
            uint32_t abase = sb + arow * 128;
            uint32_t axor = (arow & 7) << 4;
            #pragma unroll
            for (int kf = 0; kf < 4; kf++) {
                uint32_t addr = abase + ((kf * 32 + (lane >> 4) * 16) ^ axor);
                ldsm4(ql[mf][kf][0], ql[mf][kf][1], ql[mf][kf][2], ql[mf][kf][3], addr);
            }
        }
        __syncthreads();   // done reading buf0 region before cp.async overwrites it
    }

    // ---------------- persistent state ----------------
    float o[2][8][4];
    #pragma unroll
    for (int mf = 0; mf < 2; mf++)
        #pragma unroll
        for (int i = 0; i < 8; i++)
            #pragma unroll
            for (int j = 0; j < 4; j++) o[mf][i][j] = 0.0f;
    float lsum[2][2] = {{0.0f, 0.0f}, {0.0f, 0.0f}};

    // GEMM1 B addresses: this warp's key half only (kh*32 rows -> +kh*4096 bytes)
    const uint32_t lxor = (lane & 7) << 4;
    const uint32_t g1k = (uint32_t)(kh * 32 + (lane & 7)) * 128;
    const uint32_t g1a = sb + g1k + (((lane >> 3) * 16) ^ lxor);
    const uint32_t g1b = sb + g1k + ((64 + (lane >> 3) * 16) ^ lxor);
    // GEMM2 (trans): key-row base; in-row offset XORed per fragment
    const uint32_t g2rowbase = sb + (uint32_t)(kh * 32 + (lane & 7) + 8 * ((lane >> 3) & 1)) * 128;
    const uint32_t g2klo = (lane >> 4) * 16;

    // cp.async chunk coords (2 chunks per tensor per tile; 512 x 16B chunks per tensor)
    const int id0 = tid, id1 = tid + 256;
    const int r0c = id0 >> 3, c0c = id0 & 7;
    const int r1c = id1 >> 3, c1c = id1 & 7;
    const uint32_t d0 = r0c * 128 + ((c0c * 16) ^ ((r0c & 7) << 4));
    const uint32_t d1 = r1c * 128 + ((c1c * 16) ^ ((r1c & 7) << 4));
    const uint32_t s0 = r0c * 32 + c0c * 4;
    const uint32_t s1 = r1c * 32 + c1c * 4;

    // prologue: issue tile 0 into buf 0
    {
        size_t g = vbase;
        cpasync16(sb + d0, g_vh + g + s0);
        cpasync16(sb + VL_OFF + d0, g_vl + g + s0);
        cpasync16(sb + d1, g_vh + g + s1);
        cpasync16(sb + VL_OFF + d1, g_vl + g + s1);
        asm volatile("cp.async.commit_group;" ::: "memory");
    }

    for (int t = 0; t < NT; t++) {
        asm volatile("cp.async.wait_group 0;" ::: "memory");
        __syncthreads();
        if (t + 1 < NT) {
            uint32_t nb = sb + ((t + 1) & 1) * BUF_STRIDE;
            size_t g = vbase + (size_t)(t + 1) * BN * (DH / 2);
            cpasync16(nb + d0, g_vh + g + s0);
            cpasync16(nb + VL_OFF + d0, g_vl + g + s0);
            cpasync16(nb + d1, g_vh + g + s1);
            cpasync16(nb + VL_OFF + d1, g_vl + g + s1);
            asm volatile("cp.async.commit_group;" ::: "memory");
        }
        const uint32_t bo = (t & 1) * BUF_STRIDE;

        // ---- GEMM1: S[32 x 32] = qh.vh^T + qh.vl^T + ql.vh^T (this key half) ----
        float sfrag[2][4][4];
        #pragma unroll
        for (int mf = 0; mf < 2; mf++)
            #pragma unroll
            for (int i = 0; i < 4; i++)
                #pragma unroll
                for (int j = 0; j < 4; j++) sfrag[mf][i][j] = 0.0f;
        #pragma unroll
        for (int nf = 0; nf < 4; nf++) {
            uint32_t bh[4], bh2[4], bl[4], bl2[4];
            ldsm4(bh[0], bh[1], bh2[0], bh2[1], g1a + bo + nf * 1024);
            ldsm4(bh[2], bh[3], bh2[2], bh2[3], g1b + bo + nf * 1024);
            ldsm4(bl[0], bl[1], bl2[0], bl2[1], g1a + bo + VL_OFF + nf * 1024);
            ldsm4(bl[2], bl[3], bl2[2], bl2[3], g1b + bo + VL_OFF + nf * 1024);
            #pragma unroll
            for (int mf = 0; mf < 2; mf++) {
                float* d = sfrag[mf][nf];
                mma16816(d, qh[mf][0], bh[0], bh[1]);
                mma16816(d, qh[mf][1], bh2[0], bh2[1]);
                mma16816(d, qh[mf][2], bh[2], bh[3]);
                mma16816(d, qh[mf][3], bh2[2], bh2[3]);
                mma16816(d, qh[mf][0], bl[0], bl[1]);
                mma16816(d, qh[mf][1], bl2[0], bl2[1]);
                mma16816(d, qh[mf][2], bl[2], bl[3]);
                mma16816(d, qh[mf][3], bl2[2], bl2[3]);
                mma16816(d, ql[mf][0], bh[0], bh[1]);
                mma16816(d, ql[mf][1], bh2[0], bh2[1]);
                mma16816(d, ql[mf][2], bh[2], bh[3]);
                mma16816(d, ql[mf][3], bh2[2], bh2[3]);
            }
        }

        // ---- softmax (unnormalized exp) -> P A-frags ph/pl [mf][kf][4] ----
        uint32_t ph[2][2][4], pl[2][2][4];
        #pragma unroll
        for (int mf = 0; mf < 2; mf++) {
            #pragma unroll
            for (int nf = 0; nf < 4; nf++) {
                float e0 = __expf(sfrag[mf][nf][0]);
                float e1 = __expf(sfrag[mf][nf][1]);
                float e2 = __expf(sfrag[mf][nf][2]);
                float e3 = __expf(sfrag[mf][nf][3]);
                lsum[mf][0] += e0 + e1;
                lsum[mf][1] += e2 + e3;
                uint32_t h01 = cvt2bf(e1, e0);
                uint32_t h23 = cvt2bf(e3, e2);
                float r0 = e0 - __uint_as_float(h01 << 16);
                float r1 = e1 - __uint_as_float(h01 & 0xFFFF0000u);
                float r2 = e2 - __uint_as_float(h23 << 16);
                float r3 = e3 - __uint_as_float(h23 & 0xFFFF0000u);
                int kf = nf >> 1, hh = (nf & 1) * 2;
                ph[mf][kf][hh] = h01;
                ph[mf][kf][hh + 1] = h23;
                pl[mf][kf][hh] = cvt2bf(r1, r0);
                pl[mf][kf][hh + 1] = cvt2bf(r3, r2);
            }
        }

        // ---- GEMM2: O[32 x 64] += ph.vh + ph.vl + pl.vh (trans B, this key half K=32) ----
        #pragma unroll
        for (int kf = 0; kf < 2; kf++) {
            uint32_t kfo = bo + (uint32_t)kf * 2048;
            #pragma unroll
            for (int dh2 = 0; dh2 < 4; dh2++) {
                uint32_t inrow = (uint32_t)((dh2 * 32 + g2klo) ^ lxor);
                uint32_t hr0, hr1, hr2, hr3, lr0, lr1, lr2, lr3;
                ldsm4t(hr0, hr1, hr2, hr3, g2rowbase + kfo + inrow);
                ldsm4t(lr0, lr1, lr2, lr3, g2rowbase + kfo + VL_OFF + inrow);
                #pragma unroll
                for (int mf = 0; mf < 2; mf++) {
                    mma16816(o[mf][2 * dh2], ph[mf][kf], hr0, hr1);
                    mma16816(o[mf][2 * dh2 + 1], ph[mf][kf], hr2, hr3);
                    mma16816(o[mf][2 * dh2], ph[mf][kf], lr0, lr1);
                    mma16816(o[mf][2 * dh2 + 1], ph[mf][kf], lr2, lr3);
                    mma16816(o[mf][2 * dh2], pl[mf][kf], hr0, hr1);
                    mma16816(o[mf][2 * dh2 + 1], pl[mf][kf], hr2, hr3);
                }
            }
        }
    }

    // ---------------- epilogue: combine the two key-half groups ----------------
    #pragma unroll
    for (int mf = 0; mf < 2; mf++)
        #pragma unroll
        for (int h = 0; h < 2; h++) {
            lsum[mf][h] += __shfl_xor_sync(0xffffffffu, lsum[mf][h], 1);
            lsum[mf][h] += __shfl_xor_sync(0xffffffffu, lsum[mf][h], 2);
        }

    __syncthreads();   // all tile compute done; reuse V smem for O exchange

    float* oex = (float*)smem_raw;             // [128][64] fp32 = 32KB
    float* ls  = (float*)(smem_raw + LS_OFF);  // [128] fp32

    if (kh == 0) {
        #pragma unroll
        for (int mf = 0; mf < 2; mf++) {
            int row0 = rg * 32 + mf * 16 + (lane >> 2);
            #pragma unroll
            for (int nf = 0; nf < 8; nf++) {
                int col = nf * 8 + (lane & 3) * 2;
                *(float2*)&oex[row0 * 64 + col] = make_float2(o[mf][nf][0], o[mf][nf][1]);
                *(float2*)&oex[(row0 + 8) * 64 + col] = make_float2(o[mf][nf][2], o[mf][nf][3]);
            }
            if ((lane & 3) == 0) {
                ls[row0] = lsum[mf][0];
                ls[row0 + 8] = lsum[mf][1];
            }
        }
    }
    __syncthreads();
    if (kh == 1) {
        #pragma unroll
        for (int mf = 0; mf < 2; mf++) {
            int row0 = rg * 32 + mf * 16 + (lane >> 2);
            float inv0 = 1.0f / (lsum[mf][0] + ls[row0]);
            float inv1 = 1.0f / (lsum[mf][1] + ls[row0 + 8]);
            #pragma unroll
            for (int nf = 0; nf < 8; nf++) {
                int col = nf * 8 + (lane & 3) * 2;
                float2 a = *(float2*)&oex[row0 * 64 + col];
                float2 c = *(float2*)&oex[(row0 + 8) * 64 + col];
                *(float2*)(Og + (size_t)row0 * DH + col) =
                    make_float2((o[mf][nf][0] + a.x) * inv0, (o[mf][nf][1] + a.y) * inv0);
                *(float2*)(Og + (size_t)(row0 + 8) * DH + col) =
                    make_float2((o[mf][nf][2] + c.x) * inv1, (o[mf][nf][3] + c.y) * inv1);
            }
        }
    }
}

extern "C" void kernel_launch(void* const* d_in, const int* in_sizes, int n_in,
                              void* d_out, int out_size)
{
    const float* Q = (const float*)d_in[0];   // query [4,4096,64] fp32
    const float* V = (const float*)d_in[1];   // value [4,4096,64] fp32
    float* O = (float*)d_out;                 // out   [4,4096,64] fp32

    vconv<<<(BATCH * SKV * DH / 4) / 256, 256>>>(V);

    dim3 grid(SQ / BM, BATCH);
    attn_hmma<<<grid, THREADS, SMEM_TOTAL>>>(Q, O);
}